// round 12
// baseline (speedup 1.0000x reference)
#include <cuda_runtime.h>
#include <cuda_bf16.h>
#include <cstdint>
#include <cstddef>

// Problem constants
#define B_   4
#define C_   256
#define H_   64
#define W_   64
#define OC_  256
#define K_   9
#define P_   4096          // H*W
#define CK_  2304          // C*K
#define KT_  36            // K-chunks of 64 (k-major: kt = k*4 + c/64)
#define TK_  64
#define PROW 66            // padded row width (W+2)
#define PN   4356          // (H+2)*(W+2)

// tcgen05 is arch-specific; guard out of the generic compute_103 PTX pass.
#if defined(__CUDA_ARCH_FEAT_SM103_ALL) || defined(__CUDA_ARCH_FEAT_SM100_ALL) || \
    defined(__CUDA_ARCH_FEAT_SM101_ALL) || defined(__CUDA_ARCH_SPECIFIC__) ||     \
    defined(__CUDA_ARCH_FAMILY_SPECIFIC__)
#define HAS_TC 1
#else
#define HAS_TC 0
#endif

// ---------------- scratch (device globals) ----------------
__device__ float g_sx  [B_ * K_ * P_];
__device__ float g_sy  [B_ * K_ * P_];
__device__ float g_mask[B_ * K_ * P_];
// padded NHWC transpose of x: [b][(py+1)*66+(px+1)][c], zero border (fp32)
__device__ __align__(16) float g_xtp[(size_t)B_ * PN * 256];
// bf16 hi/lo split of xtp (same layout): offconv A operand source
__device__ __align__(16) __nv_bfloat16 g_xh[(size_t)B_ * PN * 256];
__device__ __align__(16) __nv_bfloat16 g_xl[(size_t)B_ * PN * 256];
// blocked col buffers, PRE-SWIZZLED SW128: [b][kt][p][64] bf16
__device__ __align__(1024) __nv_bfloat16 g_colh[(size_t)B_ * KT_ * P_ * TK_];
__device__ __align__(1024) __nv_bfloat16 g_coll[(size_t)B_ * KT_ * P_ * TK_];
// blocked main weights, PRE-SWIZZLED SW128: [kt][oc(256)][64] bf16
__device__ __align__(1024) __nv_bfloat16 g_wh[(size_t)KT_ * OC_ * TK_];
__device__ __align__(1024) __nv_bfloat16 g_wl[(size_t)KT_ * OC_ * TK_];
// blocked offset-conv weights, PRE-SWIZZLED SW128: [kt][32 (27 padded)][64] bf16
__device__ __align__(1024) __nv_bfloat16 g_owh[(size_t)KT_ * 32 * TK_];
__device__ __align__(1024) __nv_bfloat16 g_owl[(size_t)KT_ * 32 * TK_];

// ==================== PTX helpers ====================
__device__ __forceinline__ uint32_t smem_u32(const void* p) {
    uint32_t a;
    asm("{ .reg .u64 t; cvta.to.shared.u64 t, %1; cvt.u32.u64 %0, t; }" : "=r"(a) : "l"(p));
    return a;
}
__device__ __forceinline__ uint32_t elect1() {
    uint32_t p;
    asm volatile("{\n .reg .pred p;\n elect.sync _|p, 0xFFFFFFFF;\n selp.b32 %0,1,0,p;\n}" : "=r"(p));
    return p;
}
#define MBARRIER_INIT(addr, cnt) \
    asm volatile("mbarrier.init.shared.b64 [%0], %1;" :: "r"(addr), "r"((uint32_t)(cnt)) : "memory")
#define MBAR_INVAL(addr) \
    asm volatile("mbarrier.inval.shared.b64 [%0];" :: "r"(addr) : "memory")
#define MBARRIER_EXPECT_TX(addr, bytes) \
    asm volatile("mbarrier.arrive.expect_tx.shared.b64 _, [%0], %1;" \
        :: "r"(addr), "r"((uint32_t)(bytes)) : "memory")
#define MBARRIER_WAIT_PARITY(mbar, par) do {                                   \
    uint32_t _m = (mbar); uint32_t _p = (uint32_t)(par); uint32_t _d;          \
    asm volatile("{\n .reg .pred p;\n"                                         \
        " mbarrier.try_wait.parity.acquire.cta.shared::cta.b64 p, [%1], %2;\n" \
        " selp.b32 %0, 1, 0, p;\n}" : "=r"(_d) : "r"(_m), "r"(_p) : "memory"); \
    if (!_d) {                                                                 \
        asm volatile("{\n .reg .pred P1;\n"                                    \
            "WL_%=:\n"                                                         \
            " mbarrier.try_wait.parity.acquire.cta.shared::cta.b64 P1, [%0], %1, 0x989680;\n" \
            " @P1 bra.uni WD_%=;\n bra.uni WL_%=;\nWD_%=:\n}"                  \
            :: "r"(_m), "r"(_p) : "memory");                                   \
    }                                                                          \
} while (0)
#define CP_COMMIT() asm volatile("cp.async.commit_group;" ::: "memory")
#define CP_WAIT0()  asm volatile("cp.async.wait_group 0;" ::: "memory")
#define CP_WAIT1()  asm volatile("cp.async.wait_group 1;" ::: "memory")
#define CP16(dst, src) \
    asm volatile("cp.async.cg.shared.global [%0], [%1], 16;" :: "r"((uint32_t)(dst)), "l"(src))
// TMA 1D bulk copy global -> shared with mbarrier completion
#define BULK_G2S(dst, src, sz, mb) \
    asm volatile("cp.async.bulk.shared::cluster.global.mbarrier::complete_tx::bytes [%0], [%1], %2, [%3];" \
        :: "r"((uint32_t)(dst)), "l"(src), "r"((uint32_t)(sz)), "r"((uint32_t)(mb)) : "memory")

#if HAS_TC
#define TCGEN05_ALLOC(sa, n) \
    asm volatile("tcgen05.alloc.cta_group::1.sync.aligned.shared::cta.b32 [%0], %1;" \
        :: "r"((uint32_t)(sa)), "r"((uint32_t)(n)) : "memory")
#define TCGEN05_DEALLOC(t, n) \
    asm volatile("tcgen05.dealloc.cta_group::1.sync.aligned.b32 %0, %1;" :: "r"(t), "r"((uint32_t)(n)))
#define TCGEN05_RELINQ() \
    asm volatile("tcgen05.relinquish_alloc_permit.cta_group::1.sync.aligned;")
#define TCGEN05_COMMIT(mbar) \
    asm volatile("tcgen05.commit.cta_group::1.mbarrier::arrive::one.shared::cluster.b64 [%0];" \
        :: "r"((uint32_t)(mbar)) : "memory")
#define TCGEN05_FENCE_AFTER()  asm volatile("tcgen05.fence::after_thread_sync;" ::: "memory")
#define TCGEN05_FENCE_BEFORE() asm volatile("tcgen05.fence::before_thread_sync;" ::: "memory")
#define TCGEN05_WAIT_LD()      asm volatile("tcgen05.wait::ld.sync.aligned;" ::: "memory")
#define TCGEN05_LD_X32(r, ta) \
    asm volatile("tcgen05.ld.sync.aligned.32x32b.x32.b32 " \
        "{%0,%1,%2,%3,%4,%5,%6,%7,%8,%9,%10,%11,%12,%13,%14,%15," \
        "%16,%17,%18,%19,%20,%21,%22,%23,%24,%25,%26,%27,%28,%29,%30,%31}, [%32];" \
        : "=r"((r)[0]),"=r"((r)[1]),"=r"((r)[2]),"=r"((r)[3]),"=r"((r)[4]),"=r"((r)[5]),"=r"((r)[6]),"=r"((r)[7]), \
          "=r"((r)[8]),"=r"((r)[9]),"=r"((r)[10]),"=r"((r)[11]),"=r"((r)[12]),"=r"((r)[13]),"=r"((r)[14]),"=r"((r)[15]), \
          "=r"((r)[16]),"=r"((r)[17]),"=r"((r)[18]),"=r"((r)[19]),"=r"((r)[20]),"=r"((r)[21]),"=r"((r)[22]),"=r"((r)[23]), \
          "=r"((r)[24]),"=r"((r)[25]),"=r"((r)[26]),"=r"((r)[27]),"=r"((r)[28]),"=r"((r)[29]),"=r"((r)[30]),"=r"((r)[31]) \
        : "r"(ta))
#endif

// SW128 K-major descriptor (layout=2, version=1, SBO=64, LBO=1)
__device__ __forceinline__ uint64_t sdesc(uint32_t addr) {
    return 0x4000404000010000ull | (uint64_t)((addr >> 4) & 0x3FFF);
}
// idesc kind::f16 bf16/f32: M=128 with N=128 / N=32
#define IDESC128_ 0x8200490u
#define IDESC32_  0x8080490u

__device__ __forceinline__ void mma_bf16_ss(uint32_t d, uint64_t ad, uint64_t bd,
                                            uint32_t idesc, uint32_t en) {
#if HAS_TC
    asm volatile("{\n .reg .pred p;\n setp.ne.u32 p, %5, 0;\n"
        " tcgen05.mma.cta_group::1.kind::f16 [%0], %1, %2, %3, {%4,%4,%4,%4}, p;\n}"
        :: "r"(d), "l"(ad), "l"(bd), "r"(idesc), "r"(0u), "r"(en) : "memory");
#endif
}

// ---------------- kernel 0a: zero borders (fp32 + bf16 hi/lo) -----------------
__global__ __launch_bounds__(64) void k_zero_border() {
    const int pos = blockIdx.x;
    const int b   = blockIdx.y;
    int row, col;
    if (pos < 66)       { row = 0;  col = pos; }
    else if (pos < 132) { row = 65; col = pos - 66; }
    else if (pos < 196) { row = pos - 132 + 1; col = 0; }
    else                { row = pos - 196 + 1; col = 65; }
    const size_t pix = (size_t)b * PN + row * PROW + col;
    ((float4*)(g_xtp + pix * 256))[threadIdx.x] = make_float4(0.f, 0.f, 0.f, 0.f);
    ((uint2*)((char*)g_xh + pix * 512))[threadIdx.x] = make_uint2(0u, 0u);
    ((uint2*)((char*)g_xl + pix * 512))[threadIdx.x] = make_uint2(0u, 0u);
}

// ---------------- kernel 0b: NCHW -> padded NHWC transpose + bf16 split ------
__global__ __launch_bounds__(256) void k_transpose(const float* __restrict__ x) {
    __shared__ float s[64][129];
    const int py = blockIdx.x;
    const int c0 = blockIdx.y * 128;
    const int b  = blockIdx.z;
    const int tid = threadIdx.x;

    const float* xb = x + ((size_t)b * C_ + c0) * P_ + py * 64;
    const int px = tid & 63;
    const int cb = tid >> 6;
#pragma unroll
    for (int it = 0; it < 32; it++) {
        const int c = it * 4 + cb;
        s[px][c] = xb[(size_t)c * P_ + px];
    }
    __syncthreads();

    float* ob = g_xtp + (size_t)b * PN * 256;
    __nv_bfloat16* xh = g_xh + (size_t)b * PN * 256;
    __nv_bfloat16* xl = g_xl + (size_t)b * PN * 256;
#pragma unroll
    for (int it = 0; it < 32; it++) {
        const int idx = it * 256 + tid;
        const int pxo = idx >> 7;
        const int c   = idx & 127;
        const float v = s[pxo][c];
        const size_t o = ((size_t)(py + 1) * PROW + pxo + 1) * 256 + c0 + c;
        ob[o] = v;
        const __nv_bfloat16 h = __float2bfloat16(v);
        xh[o] = h;
        xl[o] = __float2bfloat16(v - __bfloat162float(h));
    }
}

// ---------------- kernel 1: merged weight splits (all pre-swizzled) ----------
__global__ __launch_bounds__(256) void k_split(const float* __restrict__ w,
                                               const float* __restrict__ ow) {
    const int bid = blockIdx.x;
    const int tid = threadIdx.x;
    if (bid < 2304) {
        const int idx = bid * 256 + tid;       // [kt][oc][ck]
        const int ck = idx & 63;
        const int oc = (idx >> 6) & 255;
        const int kt = idx >> 14;
        const int k  = kt >> 2;
        const int c  = ((kt & 3) << 6) + ck;
        const float v = w[(size_t)oc * CK_ + c * 9 + k];
        const __nv_bfloat16 h = __float2bfloat16(v);
        const __nv_bfloat16 l = __float2bfloat16(v - __bfloat162float(h));
        const uint32_t inrow = ((uint32_t)ck * 2u) ^ (((uint32_t)oc & 7u) << 4);
        const size_t byteoff = ((size_t)kt * OC_ + oc) * 128u + inrow;
        *(__nv_bfloat16*)((char*)g_wh + byteoff) = h;
        *(__nv_bfloat16*)((char*)g_wl + byteoff) = l;
    } else {
        const int idx = (bid - 2304) * 256 + tid;  // [kt][n(32)][ck]
        const int kt = idx >> 11;
        const int n  = (idx >> 6) & 31;
        const int ck = idx & 63;
        const int k  = kt >> 2;
        const int c  = ((kt & 3) << 6) + ck;
        const float v = (n < 27) ? ow[(size_t)n * CK_ + c * 9 + k] : 0.f;
        const __nv_bfloat16 h = __float2bfloat16(v);
        const __nv_bfloat16 l = __float2bfloat16(v - __bfloat162float(h));
        const uint32_t inrow = ((uint32_t)ck * 2u) ^ (((uint32_t)n & 7u) << 4);
        const size_t byteoff = ((size_t)kt * 32 + n) * 128u + inrow;
        *(__nv_bfloat16*)((char*)g_owh + byteoff) = h;
        *(__nv_bfloat16*)((char*)g_owl + byteoff) = l;
    }
}

// ---------------- kernel 3: offset conv, double-buffered cp.async pipeline ---
// 18 double-chunks. Stage: Ah0 16K | Al0 16K | Ah1 16K | Al1 16K |
// Bh0 4K | Bl0 4K | Bh1 4K | Bl1 4K = 80K; two stages. One full iteration of
// cp.async slack: groups for kt2 and kt2+1 in flight; wait_group 1 each iter.
#define OFF_STG 81920u
#define OFF_SMEM (1024 + 2 * 81920)

__global__ __launch_bounds__(256, 1) void k_offconv_tc(const float* __restrict__ ob) {
#if HAS_TC
    extern __shared__ char smem[];
    const uint32_t sb = smem_u32(smem);
    const int tid = (int)threadIdx.x;
    const int wid = tid >> 5, lid = tid & 31;
    const int p0  = blockIdx.x * 128;
    const int b   = blockIdx.y;
    const uint32_t mb[2] = { sb + 16, sb + 24 };
    const uint32_t T0 = sb + 1024;

    if (tid == 0) { MBARRIER_INIT(mb[0], 1); MBARRIER_INIT(mb[1], 1); }
    if (wid == 0) TCGEN05_ALLOC(sb, 64);
    __syncthreads();
    uint32_t tmem;
    asm volatile("ld.shared.b32 %0, [%1];" : "=r"(tmem) : "r"(sb));

    const char* xhB = (const char*)g_xh + (size_t)b * PN * 512;
    const char* xlB = (const char*)g_xl + (size_t)b * PN * 512;

    auto cp_group2 = [&](uint32_t tb, int kt2) {
#pragma unroll
        for (int sub = 0; sub < 2; sub++) {
            const int kt  = kt2 * 2 + sub;
            const int k   = kt >> 2;
            const int c0b = (kt & 3) << 7;          // byte offset in 512B pixel row
            const int ky  = k / 3, kx = k - ky * 3;
            const uint32_t abase = tb + (uint32_t)sub * 32768u;
            const uint32_t bbase = tb + 65536u + (uint32_t)sub * 8192u;
#pragma unroll
            for (int i = 0; i < 4; i++) {
                const int u = tid + i * 256;         // 0..1023 16B units
                const int r = u >> 3, j = u & 7;
                const int p = p0 + r;
                const int py = p >> 6, px = p & 63;
                const size_t so = (size_t)((py + ky) * PROW + px + kx) * 512 + c0b + j * 16;
                const uint32_t d = abase + (uint32_t)r * 128u + (((uint32_t)j * 16u) ^ (((uint32_t)r & 7u) << 4));
                CP16(d,           xhB + so);
                CP16(d + 16384u,  xlB + so);
            }
            CP16(bbase + tid * 16,          (const char*)g_owh + (size_t)kt * 4096 + tid * 16);
            CP16(bbase + 4096u + tid * 16,  (const char*)g_owl + (size_t)kt * 4096 + tid * 16);
        }
        CP_COMMIT();
    };

    // two groups in flight from the start
    cp_group2(T0, 0);
    cp_group2(T0 + OFF_STG, 1);

    int ph[2] = {0, 0};
    for (int kt2 = 0; kt2 < 18; kt2++) {
        const int cur = kt2 & 1;
        if (kt2 == 17) { CP_WAIT0(); } else { CP_WAIT1(); }   // group(kt2) landed
        __syncthreads();
        if (wid == 0 && elect1()) {
            asm volatile("fence.proxy.async;" ::: "memory");
            const uint32_t tb = T0 + (uint32_t)cur * OFF_STG;
#pragma unroll
            for (int sub = 0; sub < 2; sub++) {
                const uint64_t ah = sdesc(tb + (uint32_t)sub * 32768u);
                const uint64_t al = sdesc(tb + (uint32_t)sub * 32768u + 16384u);
                const uint64_t bh = sdesc(tb + 65536u + (uint32_t)sub * 8192u);
                const uint64_t bl = sdesc(tb + 65536u + (uint32_t)sub * 8192u + 4096u);
#pragma unroll
                for (int s = 0; s < 4; s++) mma_bf16_ss(tmem, ah + 2 * s, bh + 2 * s, IDESC32_, (s == 0 && sub == 0 && kt2 == 0) ? 0u : 1u);
#pragma unroll
                for (int s = 0; s < 4; s++) mma_bf16_ss(tmem, ah + 2 * s, bl + 2 * s, IDESC32_, 1u);
#pragma unroll
                for (int s = 0; s < 4; s++) mma_bf16_ss(tmem, al + 2 * s, bh + 2 * s, IDESC32_, 1u);
            }
            TCGEN05_COMMIT(mb[cur]);
        }
        if (kt2 + 2 < 18) {
            // wait MMA(kt2) completion before overwriting stage cur with group kt2+2
            MBARRIER_WAIT_PARITY(mb[cur], ph[cur]); ph[cur] ^= 1;
            cp_group2(T0 + (uint32_t)cur * OFF_STG, kt2 + 2);
        }
    }
    // final MMAs: kt2=16 (stage0, phase ph[0]) and kt2=17 (stage1, phase ph[1])
    MBARRIER_WAIT_PARITY(mb[0], ph[0]);
    MBARRIER_WAIT_PARITY(mb[1], ph[1]);
    TCGEN05_FENCE_AFTER();

    if (wid < 4) {
        uint32_t r[32];
        TCGEN05_LD_X32(r, tmem);
        TCGEN05_WAIT_LD();
        TCGEN05_FENCE_BEFORE();

        const int p  = p0 + wid * 32 + lid;
        const int py = p >> 6, px = p & 63;
#pragma unroll
        for (int k = 0; k < 9; k++) {
            const int kx = k % 3, ky = k / 3;
            const float ox = __uint_as_float(r[k])      + ob[k];
            const float oy = __uint_as_float(r[9 + k])  + ob[9 + k];
            const float om = __uint_as_float(r[18 + k]) + ob[18 + k];
            const int gi = (b * 9 + k) * P_ + p;
            g_sx[gi]   = (float)(px - 1 + (kx - 1)) + ox;
            g_sy[gi]   = (float)(py - 1 + (ky - 1)) + oy;
            g_mask[gi] = 1.f / (1.f + expf(-om));
        }
    }

    __syncthreads();
    if (tid == 0) { MBAR_INVAL(mb[0]); MBAR_INVAL(mb[1]); }
    if (wid == 0) { TCGEN05_RELINQ(); TCGEN05_DEALLOC(tmem, 64); }
#endif
}

// ---------------- kernel 4: coalesced bilinear im2col, PRE-SWIZZLED out ------
__global__ __launch_bounds__(256) void k_im2col_tc() {
    __shared__ uint32_t sOff[4][128];
    __shared__ float    sWgt[4][128];
    const int tid = threadIdx.x;
    const int p0  = blockIdx.x * 128;
    const int kt  = blockIdx.y;
    const int b   = blockIdx.z;
    const int k   = kt >> 2;
    const int c0  = (kt & 3) << 6;

    if (tid < 128) {
        const int gi = (b * 9 + k) * P_ + p0 + tid;
        const float sx = g_sx[gi], sy = g_sy[gi], m = g_mask[gi];
        const float x0f = floorf(sx), y0f = floorf(sy);
        const int x0 = (int)x0f, y0 = (int)y0f;
        const float wx1 = sx - x0f, wy1 = sy - y0f;
        const float wx0 = 1.f - wx1, wy0 = 1.f - wy1;
        const bool vx0 = (x0 >= 0) && (x0 < W_), vx1 = (x0 + 1 >= 0) && (x0 + 1 < W_);
        const bool vy0 = (y0 >= 0) && (y0 < H_), vy1 = (y0 + 1 >= 0) && (y0 + 1 < H_);
        const int cx0 = min(max(x0, 0), W_ - 1), cx1 = min(max(x0 + 1, 0), W_ - 1);
        const int cy0 = min(max(y0, 0), H_ - 1), cy1 = min(max(y0 + 1, 0), H_ - 1);
        sOff[0][tid] = (uint32_t)((((cy0 + 1) * PROW + cx0 + 1) * 256 + c0) * 4);
        sOff[1][tid] = (uint32_t)((((cy0 + 1) * PROW + cx1 + 1) * 256 + c0) * 4);
        sOff[2][tid] = (uint32_t)((((cy1 + 1) * PROW + cx0 + 1) * 256 + c0) * 4);
        sOff[3][tid] = (uint32_t)((((cy1 + 1) * PROW + cx1 + 1) * 256 + c0) * 4);
        sWgt[0][tid] = wx0 * wy0 * ((vx0 && vy0) ? m : 0.f);
        sWgt[1][tid] = wx1 * wy0 * ((vx1 && vy0) ? m : 0.f);
        sWgt[2][tid] = wx0 * wy1 * ((vx0 && vy1) ? m : 0.f);
        sWgt[3][tid] = wx1 * wy1 * ((vx1 && vy1) ? m : 0.f);
    }
    __syncthreads();

    const char* xb = (const char*)(g_xtp + (size_t)b * PN * 256);
    const int cp = tid & 31;
    char* ohb = (char*)g_colh + (((size_t)b * KT_ + kt) * P_ + p0) * 128;
    char* olb = (char*)g_coll + (((size_t)b * KT_ + kt) * P_ + p0) * 128;

#pragma unroll
    for (int it = 0; it < 16; it++) {
        const int pl = it * 8 + (tid >> 5);
        const uint32_t cb = (uint32_t)cp * 8u;
        const float2 a0 = *(const float2*)(xb + sOff[0][pl] + cb);
        const float2 a1 = *(const float2*)(xb + sOff[1][pl] + cb);
        const float2 a2 = *(const float2*)(xb + sOff[2][pl] + cb);
        const float2 a3 = *(const float2*)(xb + sOff[3][pl] + cb);
        const float w0 = sWgt[0][pl], w1 = sWgt[1][pl], w2 = sWgt[2][pl], w3 = sWgt[3][pl];
        const float v0 = w0 * a0.x + w1 * a1.x + w2 * a2.x + w3 * a3.x;
        const float v1 = w0 * a0.y + w1 * a1.y + w2 * a2.y + w3 * a3.y;
        const __nv_bfloat16 h0 = __float2bfloat16(v0);
        const __nv_bfloat16 h1 = __float2bfloat16(v1);
        __nv_bfloat162 hh; hh.x = h0; hh.y = h1;
        __nv_bfloat162 ll;
        ll.x = __float2bfloat16(v0 - __bfloat162float(h0));
        ll.y = __float2bfloat16(v1 - __bfloat162float(h1));
        const uint32_t off = (uint32_t)pl * 128u + (((uint32_t)cp * 4u) ^ (((uint32_t)pl & 7u) << 4));
        *(uint32_t*)(ohb + off) = *(const uint32_t*)&hh;
        *(uint32_t*)(olb + off) = *(const uint32_t*)&ll;
    }
}

// ---------------- kernel 5: tcgen05 GEMM, M=256 per CTA, TMA producer --------
#define MAIN_STG 98304u
#define STG_BYTES 98304u

__global__ __launch_bounds__(256, 1) void k_gemm_tc(const float* __restrict__ bias,
                                                    float* __restrict__ out) {
#if HAS_TC
    extern __shared__ char smem[];
    const uint32_t sb = smem_u32(smem);
    const int tid = (int)threadIdx.x;
    const int wid = tid >> 5, lid = tid & 31;
    const int p0  = blockIdx.x * 128;
    const int b   = blockIdx.y;
    const uint32_t mbL[2] = { sb + 16, sb + 24 };
    const uint32_t mbM[2] = { sb + 32, sb + 40 };
    const uint32_t T0 = sb + 1024;

    if (tid == 0) {
        MBARRIER_INIT(mbL[0], 1); MBARRIER_INIT(mbL[1], 1);
        MBARRIER_INIT(mbM[0], 1); MBARRIER_INIT(mbM[1], 1);
    }
    if (wid == 0) TCGEN05_ALLOC(sb, 256);
    __syncthreads();
    uint32_t tmem;
    asm volatile("ld.shared.b32 %0, [%1];" : "=r"(tmem) : "r"(sb));

    if (wid == 0 && elect1()) {
        auto load = [&](int s, int kt) {
            const uint32_t tb = T0 + (uint32_t)s * MAIN_STG;
            const char* ah = (const char*)g_wh + (size_t)kt * OC_ * 128u;
            const char* al = (const char*)g_wl + (size_t)kt * OC_ * 128u;
            const char* bh = (const char*)g_colh + (((size_t)b * KT_ + kt) * P_ + p0) * 128u;
            const char* bl = (const char*)g_coll + (((size_t)b * KT_ + kt) * P_ + p0) * 128u;
            MBARRIER_EXPECT_TX(mbL[s], STG_BYTES);
            BULK_G2S(tb,           ah, 32768u, mbL[s]);
            BULK_G2S(tb + 32768u,  al, 32768u, mbL[s]);
            BULK_G2S(tb + 65536u,  bh, 16384u, mbL[s]);
            BULK_G2S(tb + 81920u,  bl, 16384u, mbL[s]);
        };
        load(0, 0);
        load(1, 1);

        int lph[2] = {0, 0}, mph[2] = {0, 0};
        for (int kt = 0; kt < KT_; kt++) {
            const int cur = kt & 1;
            MBARRIER_WAIT_PARITY(mbL[cur], lph[cur]); lph[cur] ^= 1;
            const uint32_t tb = T0 + (uint32_t)cur * MAIN_STG;
            const uint64_t bh = sdesc(tb + 65536u);
            const uint64_t bl = sdesc(tb + 81920u);
#pragma unroll
            for (int t = 0; t < 2; t++) {
                const uint64_t ah = sdesc(tb + (uint32_t)t * 16384u);
                const uint64_t al = sdesc(tb + 32768u + (uint32_t)t * 16384u);
                const uint32_t dt = tmem + (uint32_t)t * 128u;
#pragma unroll
                for (int s = 0; s < 4; s++) mma_bf16_ss(dt, ah + 2 * s, bh + 2 * s, IDESC128_, (s == 0 && kt == 0) ? 0u : 1u);
#pragma unroll
                for (int s = 0; s < 4; s++) mma_bf16_ss(dt, ah + 2 * s, bl + 2 * s, IDESC128_, 1u);
#pragma unroll
                for (int s = 0; s < 4; s++) mma_bf16_ss(dt, al + 2 * s, bh + 2 * s, IDESC128_, 1u);
            }
            TCGEN05_COMMIT(mbM[cur]);
            if (kt + 2 < KT_) {
                MBARRIER_WAIT_PARITY(mbM[cur], mph[cur]); mph[cur] ^= 1;
                load(cur, kt + 2);
            }
        }
        MBARRIER_WAIT_PARITY(mbM[0], mph[0]);
        MBARRIER_WAIT_PARITY(mbM[1], mph[1]);
    }
    __syncthreads();
    TCGEN05_FENCE_AFTER();

    const int tile = wid >> 2, sub = wid & 3;
    const int oc = tile * 128 + sub * 32 + lid;
    const float bv = bias[oc];
    float* op = out + ((size_t)b * OC_ + oc) * P_ + p0;
#pragma unroll
    for (int j = 0; j < 4; j++) {
        uint32_t r[32];
        TCGEN05_LD_X32(r, tmem + tile * 128 + j * 32);
        TCGEN05_WAIT_LD();
#pragma unroll
        for (int c = 0; c < 32; c += 4) {
            float4 v;
            v.x = __uint_as_float(r[c + 0]) + bv;
            v.y = __uint_as_float(r[c + 1]) + bv;
            v.z = __uint_as_float(r[c + 2]) + bv;
            v.w = __uint_as_float(r[c + 3]) + bv;
            *(float4*)(op + j * 32 + c) = v;
        }
    }
    TCGEN05_FENCE_BEFORE();
    __syncthreads();
    if (tid == 0) {
        MBAR_INVAL(mbL[0]); MBAR_INVAL(mbL[1]);
        MBAR_INVAL(mbM[0]); MBAR_INVAL(mbM[1]);
    }
    if (wid == 0) { TCGEN05_RELINQ(); TCGEN05_DEALLOC(tmem, 256); }
#endif
}

// ---------------- launch ----------------
extern "C" void kernel_launch(void* const* d_in, const int* in_sizes, int n_in,
                              void* d_out, int out_size) {
    const float* x    = (const float*)d_in[0];
    const float* ow   = (const float*)d_in[1];
    const float* ob   = (const float*)d_in[2];
    const float* wgt  = (const float*)d_in[3];
    const float* bias = (const float*)d_in[4];
    float* out = (float*)d_out;

    cudaFuncSetAttribute(k_gemm_tc,    cudaFuncAttributeMaxDynamicSharedMemorySize, 197632);
    cudaFuncSetAttribute(k_offconv_tc, cudaFuncAttributeMaxDynamicSharedMemorySize, OFF_SMEM);

    k_zero_border<<<dim3(260, B_), 64>>>();
    k_transpose<<<dim3(64, 2, B_), 256>>>(x);
    k_split<<<2592, 256>>>(wgt, ow);
    k_offconv_tc<<<dim3(32, B_), 256, OFF_SMEM>>>(ob);
    k_im2col_tc<<<dim3(P_ / 128, KT_, B_), 256>>>();
    k_gemm_tc<<<dim3(P_ / 128, B_), 256, 197632>>>(bias, out);
}

// round 13
// speedup vs baseline: 1.1011x; 1.1011x over previous
#include <cuda_runtime.h>
#include <cuda_bf16.h>
#include <cstdint>
#include <cstddef>

// Problem constants
#define B_   4
#define C_   256
#define H_   64
#define W_   64
#define OC_  256
#define K_   9
#define P_   4096          // H*W
#define CK_  2304          // C*K
#define KT_  36            // K-chunks of 64 (k-major: kt = k*4 + c/64)
#define TK_  64
#define PROW 66            // padded row width (W+2)
#define PN   4356          // (H+2)*(W+2)

// tcgen05 is arch-specific; guard out of the generic compute_103 PTX pass.
#if defined(__CUDA_ARCH_FEAT_SM103_ALL) || defined(__CUDA_ARCH_FEAT_SM100_ALL) || \
    defined(__CUDA_ARCH_FEAT_SM101_ALL) || defined(__CUDA_ARCH_SPECIFIC__) ||     \
    defined(__CUDA_ARCH_FAMILY_SPECIFIC__)
#define HAS_TC 1
#else
#define HAS_TC 0
#endif

// ---------------- scratch (device globals) ----------------
__device__ float g_sx  [B_ * K_ * P_];
__device__ float g_sy  [B_ * K_ * P_];
__device__ float g_mask[B_ * K_ * P_];
// padded NHWC transpose of x: [b][(py+1)*66+(px+1)][c], zero border (fp32)
__device__ __align__(16) float g_xtp[(size_t)B_ * PN * 256];
// bf16 hi/lo split of xtp (same layout): offconv A operand source
__device__ __align__(16) __nv_bfloat16 g_xh[(size_t)B_ * PN * 256];
__device__ __align__(16) __nv_bfloat16 g_xl[(size_t)B_ * PN * 256];
// blocked col buffers, PRE-SWIZZLED SW128: [b][kt][p][64] bf16
__device__ __align__(1024) __nv_bfloat16 g_colh[(size_t)B_ * KT_ * P_ * TK_];
__device__ __align__(1024) __nv_bfloat16 g_coll[(size_t)B_ * KT_ * P_ * TK_];
// blocked main weights, PRE-SWIZZLED SW128: [kt][oc(256)][64] bf16
__device__ __align__(1024) __nv_bfloat16 g_wh[(size_t)KT_ * OC_ * TK_];
__device__ __align__(1024) __nv_bfloat16 g_wl[(size_t)KT_ * OC_ * TK_];
// blocked offset-conv weights, PRE-SWIZZLED SW128: [kt][32 (27 padded)][64] bf16
__device__ __align__(1024) __nv_bfloat16 g_owh[(size_t)KT_ * 32 * TK_];
__device__ __align__(1024) __nv_bfloat16 g_owl[(size_t)KT_ * 32 * TK_];

// ==================== PTX helpers ====================
__device__ __forceinline__ uint32_t smem_u32(const void* p) {
    uint32_t a;
    asm("{ .reg .u64 t; cvta.to.shared.u64 t, %1; cvt.u32.u64 %0, t; }" : "=r"(a) : "l"(p));
    return a;
}
__device__ __forceinline__ uint32_t elect1() {
    uint32_t p;
    asm volatile("{\n .reg .pred p;\n elect.sync _|p, 0xFFFFFFFF;\n selp.b32 %0,1,0,p;\n}" : "=r"(p));
    return p;
}
#define MBARRIER_INIT(addr, cnt) \
    asm volatile("mbarrier.init.shared.b64 [%0], %1;" :: "r"(addr), "r"((uint32_t)(cnt)) : "memory")
#define MBAR_INVAL(addr) \
    asm volatile("mbarrier.inval.shared.b64 [%0];" :: "r"(addr) : "memory")
#define MBARRIER_EXPECT_TX(addr, bytes) \
    asm volatile("mbarrier.arrive.expect_tx.shared.b64 _, [%0], %1;" \
        :: "r"(addr), "r"((uint32_t)(bytes)) : "memory")
#define MBARRIER_WAIT_PARITY(mbar, par) do {                                   \
    uint32_t _m = (mbar); uint32_t _p = (uint32_t)(par); uint32_t _d;          \
    asm volatile("{\n .reg .pred p;\n"                                         \
        " mbarrier.try_wait.parity.acquire.cta.shared::cta.b64 p, [%1], %2;\n" \
        " selp.b32 %0, 1, 0, p;\n}" : "=r"(_d) : "r"(_m), "r"(_p) : "memory"); \
    if (!_d) {                                                                 \
        asm volatile("{\n .reg .pred P1;\n"                                    \
            "WL_%=:\n"                                                         \
            " mbarrier.try_wait.parity.acquire.cta.shared::cta.b64 P1, [%0], %1, 0x989680;\n" \
            " @P1 bra.uni WD_%=;\n bra.uni WL_%=;\nWD_%=:\n}"                  \
            :: "r"(_m), "r"(_p) : "memory");                                   \
    }                                                                          \
} while (0)
#define CP_COMMIT() asm volatile("cp.async.commit_group;" ::: "memory")
#define CP_WAIT0()  asm volatile("cp.async.wait_group 0;" ::: "memory")
#define CP16(dst, src) \
    asm volatile("cp.async.cg.shared.global [%0], [%1], 16;" :: "r"((uint32_t)(dst)), "l"(src))
// TMA 1D bulk copy global -> shared with mbarrier completion
#define BULK_G2S(dst, src, sz, mb) \
    asm volatile("cp.async.bulk.shared::cluster.global.mbarrier::complete_tx::bytes [%0], [%1], %2, [%3];" \
        :: "r"((uint32_t)(dst)), "l"(src), "r"((uint32_t)(sz)), "r"((uint32_t)(mb)) : "memory")

#if HAS_TC
#define TCGEN05_ALLOC(sa, n) \
    asm volatile("tcgen05.alloc.cta_group::1.sync.aligned.shared::cta.b32 [%0], %1;" \
        :: "r"((uint32_t)(sa)), "r"((uint32_t)(n)) : "memory")
#define TCGEN05_DEALLOC(t, n) \
    asm volatile("tcgen05.dealloc.cta_group::1.sync.aligned.b32 %0, %1;" :: "r"(t), "r"((uint32_t)(n)))
#define TCGEN05_RELINQ() \
    asm volatile("tcgen05.relinquish_alloc_permit.cta_group::1.sync.aligned;")
#define TCGEN05_COMMIT(mbar) \
    asm volatile("tcgen05.commit.cta_group::1.mbarrier::arrive::one.shared::cluster.b64 [%0];" \
        :: "r"((uint32_t)(mbar)) : "memory")
#define TCGEN05_FENCE_AFTER()  asm volatile("tcgen05.fence::after_thread_sync;" ::: "memory")
#define TCGEN05_FENCE_BEFORE() asm volatile("tcgen05.fence::before_thread_sync;" ::: "memory")
#define TCGEN05_WAIT_LD()      asm volatile("tcgen05.wait::ld.sync.aligned;" ::: "memory")
#define TCGEN05_LD_X32(r, ta) \
    asm volatile("tcgen05.ld.sync.aligned.32x32b.x32.b32 " \
        "{%0,%1,%2,%3,%4,%5,%6,%7,%8,%9,%10,%11,%12,%13,%14,%15," \
        "%16,%17,%18,%19,%20,%21,%22,%23,%24,%25,%26,%27,%28,%29,%30,%31}, [%32];" \
        : "=r"((r)[0]),"=r"((r)[1]),"=r"((r)[2]),"=r"((r)[3]),"=r"((r)[4]),"=r"((r)[5]),"=r"((r)[6]),"=r"((r)[7]), \
          "=r"((r)[8]),"=r"((r)[9]),"=r"((r)[10]),"=r"((r)[11]),"=r"((r)[12]),"=r"((r)[13]),"=r"((r)[14]),"=r"((r)[15]), \
          "=r"((r)[16]),"=r"((r)[17]),"=r"((r)[18]),"=r"((r)[19]),"=r"((r)[20]),"=r"((r)[21]),"=r"((r)[22]),"=r"((r)[23]), \
          "=r"((r)[24]),"=r"((r)[25]),"=r"((r)[26]),"=r"((r)[27]),"=r"((r)[28]),"=r"((r)[29]),"=r"((r)[30]),"=r"((r)[31]) \
        : "r"(ta))
#endif

// SW128 K-major descriptor (layout=2, version=1, SBO=64, LBO=1)
__device__ __forceinline__ uint64_t sdesc(uint32_t addr) {
    return 0x4000404000010000ull | (uint64_t)((addr >> 4) & 0x3FFF);
}
// idesc kind::f16 bf16/f32: M=128 with N=128 / N=32
#define IDESC128_ 0x8200490u
#define IDESC32_  0x8080490u

__device__ __forceinline__ void mma_bf16_ss(uint32_t d, uint64_t ad, uint64_t bd,
                                            uint32_t idesc, uint32_t en) {
#if HAS_TC
    asm volatile("{\n .reg .pred p;\n setp.ne.u32 p, %5, 0;\n"
        " tcgen05.mma.cta_group::1.kind::f16 [%0], %1, %2, %3, {%4,%4,%4,%4}, p;\n}"
        :: "r"(d), "l"(ad), "l"(bd), "r"(idesc), "r"(0u), "r"(en) : "memory");
#endif
}

// ---------------- kernel 0a: zero borders (fp32 + bf16 hi/lo) -----------------
__global__ __launch_bounds__(64) void k_zero_border() {
    const int pos = blockIdx.x;
    const int b   = blockIdx.y;
    int row, col;
    if (pos < 66)       { row = 0;  col = pos; }
    else if (pos < 132) { row = 65; col = pos - 66; }
    else if (pos < 196) { row = pos - 132 + 1; col = 0; }
    else                { row = pos - 196 + 1; col = 65; }
    const size_t pix = (size_t)b * PN + row * PROW + col;
    ((float4*)(g_xtp + pix * 256))[threadIdx.x] = make_float4(0.f, 0.f, 0.f, 0.f);
    ((uint2*)((char*)g_xh + pix * 512))[threadIdx.x] = make_uint2(0u, 0u);
    ((uint2*)((char*)g_xl + pix * 512))[threadIdx.x] = make_uint2(0u, 0u);
}

// ---------------- kernel 0b: NCHW -> padded NHWC transpose + bf16 split ------
__global__ __launch_bounds__(256) void k_transpose(const float* __restrict__ x) {
    __shared__ float s[64][129];
    const int py = blockIdx.x;
    const int c0 = blockIdx.y * 128;
    const int b  = blockIdx.z;
    const int tid = threadIdx.x;

    const float* xb = x + ((size_t)b * C_ + c0) * P_ + py * 64;
    const int px = tid & 63;
    const int cb = tid >> 6;
#pragma unroll
    for (int it = 0; it < 32; it++) {
        const int c = it * 4 + cb;
        s[px][c] = xb[(size_t)c * P_ + px];
    }
    __syncthreads();

    float* ob = g_xtp + (size_t)b * PN * 256;
    __nv_bfloat16* xh = g_xh + (size_t)b * PN * 256;
    __nv_bfloat16* xl = g_xl + (size_t)b * PN * 256;
#pragma unroll
    for (int it = 0; it < 32; it++) {
        const int idx = it * 256 + tid;
        const int pxo = idx >> 7;
        const int c   = idx & 127;
        const float v = s[pxo][c];
        const size_t o = ((size_t)(py + 1) * PROW + pxo + 1) * 256 + c0 + c;
        ob[o] = v;
        const __nv_bfloat16 h = __float2bfloat16(v);
        xh[o] = h;
        xl[o] = __float2bfloat16(v - __bfloat162float(h));
    }
}

// ---------------- kernel 1: merged weight splits (all pre-swizzled) ----------
__global__ __launch_bounds__(256) void k_split(const float* __restrict__ w,
                                               const float* __restrict__ ow) {
    const int bid = blockIdx.x;
    const int tid = threadIdx.x;
    if (bid < 2304) {
        const int idx = bid * 256 + tid;       // [kt][oc][ck]
        const int ck = idx & 63;
        const int oc = (idx >> 6) & 255;
        const int kt = idx >> 14;
        const int k  = kt >> 2;
        const int c  = ((kt & 3) << 6) + ck;
        const float v = w[(size_t)oc * CK_ + c * 9 + k];
        const __nv_bfloat16 h = __float2bfloat16(v);
        const __nv_bfloat16 l = __float2bfloat16(v - __bfloat162float(h));
        const uint32_t inrow = ((uint32_t)ck * 2u) ^ (((uint32_t)oc & 7u) << 4);
        const size_t byteoff = ((size_t)kt * OC_ + oc) * 128u + inrow;
        *(__nv_bfloat16*)((char*)g_wh + byteoff) = h;
        *(__nv_bfloat16*)((char*)g_wl + byteoff) = l;
    } else {
        const int idx = (bid - 2304) * 256 + tid;  // [kt][n(32)][ck]
        const int kt = idx >> 11;
        const int n  = (idx >> 6) & 31;
        const int ck = idx & 63;
        const int k  = kt >> 2;
        const int c  = ((kt & 3) << 6) + ck;
        const float v = (n < 27) ? ow[(size_t)n * CK_ + c * 9 + k] : 0.f;
        const __nv_bfloat16 h = __float2bfloat16(v);
        const __nv_bfloat16 l = __float2bfloat16(v - __bfloat162float(h));
        const uint32_t inrow = ((uint32_t)ck * 2u) ^ (((uint32_t)n & 7u) << 4);
        const size_t byteoff = ((size_t)kt * 32 + n) * 128u + inrow;
        *(__nv_bfloat16*)((char*)g_owh + byteoff) = h;
        *(__nv_bfloat16*)((char*)g_owl + byteoff) = l;
    }
}

// ---------------- kernel 3: offset conv on tcgen05 (round-11 verbatim) -------
// 18 double-chunks. Stage: Ah0 16K | Al0 16K | Ah1 16K | Al1 16K |
// Bh0 4K | Bl0 4K | Bh1 4K | Bl1 4K = 80K; two stages.
#define OFF_STG 81920u
#define OFF_SMEM (1024 + 2 * 81920)

__global__ __launch_bounds__(256, 1) void k_offconv_tc(const float* __restrict__ ob) {
#if HAS_TC
    extern __shared__ char smem[];
    const uint32_t sb = smem_u32(smem);
    const int tid = (int)threadIdx.x;
    const int wid = tid >> 5, lid = tid & 31;
    const int p0  = blockIdx.x * 128;
    const int b   = blockIdx.y;
    const uint32_t mb0 = sb + 16, mb1 = sb + 24;
    const uint32_t T0 = sb + 1024;

    if (tid == 0) { MBARRIER_INIT(mb0, 1); MBARRIER_INIT(mb1, 1); }
    if (wid == 0) TCGEN05_ALLOC(sb, 64);
    __syncthreads();
    uint32_t tmem;
    asm volatile("ld.shared.b32 %0, [%1];" : "=r"(tmem) : "r"(sb));

    const char* xhB = (const char*)g_xh + (size_t)b * PN * 512;
    const char* xlB = (const char*)g_xl + (size_t)b * PN * 512;

    auto cp_group2 = [&](uint32_t tb, int kt2) {
#pragma unroll
        for (int sub = 0; sub < 2; sub++) {
            const int kt  = kt2 * 2 + sub;
            const int k   = kt >> 2;
            const int c0b = (kt & 3) << 7;
            const int ky  = k / 3, kx = k - ky * 3;
            const uint32_t abase = tb + (uint32_t)sub * 32768u;
            const uint32_t bbase = tb + 65536u + (uint32_t)sub * 8192u;
#pragma unroll
            for (int i = 0; i < 4; i++) {
                const int u = tid + i * 256;
                const int r = u >> 3, j = u & 7;
                const int p = p0 + r;
                const int py = p >> 6, px = p & 63;
                const size_t so = (size_t)((py + ky) * PROW + px + kx) * 512 + c0b + j * 16;
                const uint32_t d = abase + (uint32_t)r * 128u + (((uint32_t)j * 16u) ^ (((uint32_t)r & 7u) << 4));
                CP16(d,           xhB + so);
                CP16(d + 16384u,  xlB + so);
            }
            CP16(bbase + tid * 16,          (const char*)g_owh + (size_t)kt * 4096 + tid * 16);
            CP16(bbase + 4096u + tid * 16,  (const char*)g_owl + (size_t)kt * 4096 + tid * 16);
        }
        CP_COMMIT();
    };

    cp_group2(T0, 0);

    int ph[2] = {0, 0};
    for (int kt2 = 0; kt2 < 18; kt2++) {
        const int cur = kt2 & 1;
        CP_WAIT0();
        __syncthreads();
        if (wid == 0 && elect1()) {
            asm volatile("fence.proxy.async;" ::: "memory");
            const uint32_t tb = T0 + (uint32_t)cur * OFF_STG;
#pragma unroll
            for (int sub = 0; sub < 2; sub++) {
                const uint64_t ah = sdesc(tb + (uint32_t)sub * 32768u);
                const uint64_t al = sdesc(tb + (uint32_t)sub * 32768u + 16384u);
                const uint64_t bh = sdesc(tb + 65536u + (uint32_t)sub * 8192u);
                const uint64_t bl = sdesc(tb + 65536u + (uint32_t)sub * 8192u + 4096u);
#pragma unroll
                for (int s = 0; s < 4; s++) mma_bf16_ss(tmem, ah + 2 * s, bh + 2 * s, IDESC32_, (s == 0 && sub == 0 && kt2 == 0) ? 0u : 1u);
#pragma unroll
                for (int s = 0; s < 4; s++) mma_bf16_ss(tmem, ah + 2 * s, bl + 2 * s, IDESC32_, 1u);
#pragma unroll
                for (int s = 0; s < 4; s++) mma_bf16_ss(tmem, al + 2 * s, bh + 2 * s, IDESC32_, 1u);
            }
            TCGEN05_COMMIT(cur ? mb1 : mb0);
        }
        if (kt2 + 1 < 18) {
            const int nxt = cur ^ 1;
            if (kt2 >= 1) {
                if (nxt == 0) { MBARRIER_WAIT_PARITY(mb0, ph[0]); ph[0] ^= 1; }
                else          { MBARRIER_WAIT_PARITY(mb1, ph[1]); ph[1] ^= 1; }
            }
            cp_group2(T0 + (uint32_t)nxt * OFF_STG, kt2 + 1);
        }
    }
    MBARRIER_WAIT_PARITY(mb0, ph[0]);
    MBARRIER_WAIT_PARITY(mb1, ph[1]);
    TCGEN05_FENCE_AFTER();

    if (wid < 4) {
        uint32_t r[32];
        TCGEN05_LD_X32(r, tmem);
        TCGEN05_WAIT_LD();
        TCGEN05_FENCE_BEFORE();

        const int p  = p0 + wid * 32 + lid;
        const int py = p >> 6, px = p & 63;
#pragma unroll
        for (int k = 0; k < 9; k++) {
            const int kx = k % 3, ky = k / 3;
            const float ox = __uint_as_float(r[k])      + ob[k];
            const float oy = __uint_as_float(r[9 + k])  + ob[9 + k];
            const float om = __uint_as_float(r[18 + k]) + ob[18 + k];
            const int gi = (b * 9 + k) * P_ + p;
            g_sx[gi]   = (float)(px - 1 + (kx - 1)) + ox;
            g_sy[gi]   = (float)(py - 1 + (ky - 1)) + oy;
            g_mask[gi] = 1.f / (1.f + expf(-om));
        }
    }

    __syncthreads();
    if (tid == 0) { MBAR_INVAL(mb0); MBAR_INVAL(mb1); }
    if (wid == 0) { TCGEN05_RELINQ(); TCGEN05_DEALLOC(tmem, 64); }
#endif
}

// ---------------- kernel 4: bilinear im2col, 4-channel threads ----------------
__global__ __launch_bounds__(256) void k_im2col_tc() {
    __shared__ uint32_t sOff[4][128];
    __shared__ float    sWgt[4][128];
    const int tid = threadIdx.x;
    const int p0  = blockIdx.x * 128;
    const int kt  = blockIdx.y;
    const int b   = blockIdx.z;
    const int k   = kt >> 2;
    const int c0  = (kt & 3) << 6;

    if (tid < 128) {
        const int gi = (b * 9 + k) * P_ + p0 + tid;
        const float sx = g_sx[gi], sy = g_sy[gi], m = g_mask[gi];
        const float x0f = floorf(sx), y0f = floorf(sy);
        const int x0 = (int)x0f, y0 = (int)y0f;
        const float wx1 = sx - x0f, wy1 = sy - y0f;
        const float wx0 = 1.f - wx1, wy0 = 1.f - wy1;
        const bool vx0 = (x0 >= 0) && (x0 < W_), vx1 = (x0 + 1 >= 0) && (x0 + 1 < W_);
        const bool vy0 = (y0 >= 0) && (y0 < H_), vy1 = (y0 + 1 >= 0) && (y0 + 1 < H_);
        const int cx0 = min(max(x0, 0), W_ - 1), cx1 = min(max(x0 + 1, 0), W_ - 1);
        const int cy0 = min(max(y0, 0), H_ - 1), cy1 = min(max(y0 + 1, 0), H_ - 1);
        sOff[0][tid] = (uint32_t)((((cy0 + 1) * PROW + cx0 + 1) * 256 + c0) * 4);
        sOff[1][tid] = (uint32_t)((((cy0 + 1) * PROW + cx1 + 1) * 256 + c0) * 4);
        sOff[2][tid] = (uint32_t)((((cy1 + 1) * PROW + cx0 + 1) * 256 + c0) * 4);
        sOff[3][tid] = (uint32_t)((((cy1 + 1) * PROW + cx1 + 1) * 256 + c0) * 4);
        sWgt[0][tid] = wx0 * wy0 * ((vx0 && vy0) ? m : 0.f);
        sWgt[1][tid] = wx1 * wy0 * ((vx1 && vy0) ? m : 0.f);
        sWgt[2][tid] = wx0 * wy1 * ((vx0 && vy1) ? m : 0.f);
        sWgt[3][tid] = wx1 * wy1 * ((vx1 && vy1) ? m : 0.f);
    }
    __syncthreads();

    const char* xb = (const char*)(g_xtp + (size_t)b * PN * 256);
    const int cq = tid & 15;              // channel quad 0..15 (4 ch each)
    const int r0 = tid >> 4;              // 0..15
    char* ohb = (char*)g_colh + (((size_t)b * KT_ + kt) * P_ + p0) * 128;
    char* olb = (char*)g_coll + (((size_t)b * KT_ + kt) * P_ + p0) * 128;

#pragma unroll
    for (int it = 0; it < 8; it++) {
        const int pl = it * 16 + r0;
        const uint32_t cb = (uint32_t)cq * 16u;
        const float4 a0 = *(const float4*)(xb + sOff[0][pl] + cb);
        const float4 a1 = *(const float4*)(xb + sOff[1][pl] + cb);
        const float4 a2 = *(const float4*)(xb + sOff[2][pl] + cb);
        const float4 a3 = *(const float4*)(xb + sOff[3][pl] + cb);
        const float w0 = sWgt[0][pl], w1 = sWgt[1][pl], w2 = sWgt[2][pl], w3 = sWgt[3][pl];
        const float v0 = w0 * a0.x + w1 * a1.x + w2 * a2.x + w3 * a3.x;
        const float v1 = w0 * a0.y + w1 * a1.y + w2 * a2.y + w3 * a3.y;
        const float v2 = w0 * a0.z + w1 * a1.z + w2 * a2.z + w3 * a3.z;
        const float v3 = w0 * a0.w + w1 * a1.w + w2 * a2.w + w3 * a3.w;
        __nv_bfloat162 h0, h1, l0, l1;
        h0.x = __float2bfloat16(v0); h0.y = __float2bfloat16(v1);
        h1.x = __float2bfloat16(v2); h1.y = __float2bfloat16(v3);
        l0.x = __float2bfloat16(v0 - __bfloat162float(h0.x));
        l0.y = __float2bfloat16(v1 - __bfloat162float(h0.y));
        l1.x = __float2bfloat16(v2 - __bfloat162float(h1.x));
        l1.y = __float2bfloat16(v3 - __bfloat162float(h1.y));
        const uint32_t off = (uint32_t)pl * 128u + (((uint32_t)cq * 8u) ^ (((uint32_t)pl & 7u) << 4));
        uint2 hv = make_uint2(*(uint32_t*)&h0, *(uint32_t*)&h1);
        uint2 lv = make_uint2(*(uint32_t*)&l0, *(uint32_t*)&l1);
        *(uint2*)(ohb + off) = hv;
        *(uint2*)(olb + off) = lv;
    }
}

// ---------------- kernel 5: tcgen05 GEMM, hi/lo split stage barriers ---------
// Stage: Ah 32K | Bh 16K | Al 32K | Bl 16K = 96K; two stages.
#define MAIN_STG 98304u

__global__ __launch_bounds__(256, 1) void k_gemm_tc(const float* __restrict__ bias,
                                                    float* __restrict__ out) {
#if HAS_TC
    extern __shared__ char smem[];
    const uint32_t sb = smem_u32(smem);
    const int tid = (int)threadIdx.x;
    const int wid = tid >> 5, lid = tid & 31;
    const int p0  = blockIdx.x * 128;
    const int b   = blockIdx.y;
    const uint32_t mbH[2] = { sb + 16, sb + 24 };
    const uint32_t mbLo[2] = { sb + 32, sb + 40 };
    const uint32_t mbM[2] = { sb + 48, sb + 56 };
    const uint32_t T0 = sb + 1024;

    if (tid == 0) {
        MBARRIER_INIT(mbH[0], 1);  MBARRIER_INIT(mbH[1], 1);
        MBARRIER_INIT(mbLo[0], 1); MBARRIER_INIT(mbLo[1], 1);
        MBARRIER_INIT(mbM[0], 1);  MBARRIER_INIT(mbM[1], 1);
    }
    if (wid == 0) TCGEN05_ALLOC(sb, 256);
    __syncthreads();
    uint32_t tmem;
    asm volatile("ld.shared.b32 %0, [%1];" : "=r"(tmem) : "r"(sb));

    if (wid == 0 && elect1()) {
        auto load = [&](int s, int kt) {
            const uint32_t tb = T0 + (uint32_t)s * MAIN_STG;
            const char* ah = (const char*)g_wh + (size_t)kt * OC_ * 128u;
            const char* al = (const char*)g_wl + (size_t)kt * OC_ * 128u;
            const char* bh = (const char*)g_colh + (((size_t)b * KT_ + kt) * P_ + p0) * 128u;
            const char* bl = (const char*)g_coll + (((size_t)b * KT_ + kt) * P_ + p0) * 128u;
            MBARRIER_EXPECT_TX(mbH[s], 49152u);
            BULK_G2S(tb,           ah, 32768u, mbH[s]);
            BULK_G2S(tb + 32768u,  bh, 16384u, mbH[s]);
            MBARRIER_EXPECT_TX(mbLo[s], 49152u);
            BULK_G2S(tb + 49152u,  al, 32768u, mbLo[s]);
            BULK_G2S(tb + 81920u,  bl, 16384u, mbLo[s]);
        };
        load(0, 0);
        load(1, 1);

        int hph[2] = {0, 0}, lph[2] = {0, 0}, mph[2] = {0, 0};
        for (int kt = 0; kt < KT_; kt++) {
            const int cur = kt & 1;
            const uint32_t tb = T0 + (uint32_t)cur * MAIN_STG;
            const uint64_t bh = sdesc(tb + 32768u);
            const uint64_t bl = sdesc(tb + 81920u);
            // hi part first: start tensor work after only 48KB landed
            MBARRIER_WAIT_PARITY(mbH[cur], hph[cur]); hph[cur] ^= 1;
#pragma unroll
            for (int t = 0; t < 2; t++) {
                const uint64_t ah = sdesc(tb + (uint32_t)t * 16384u);
                const uint32_t dt = tmem + (uint32_t)t * 128u;
#pragma unroll
                for (int s = 0; s < 4; s++) mma_bf16_ss(dt, ah + 2 * s, bh + 2 * s, IDESC128_, (s == 0 && kt == 0) ? 0u : 1u);
            }
            MBARRIER_WAIT_PARITY(mbLo[cur], lph[cur]); lph[cur] ^= 1;
#pragma unroll
            for (int t = 0; t < 2; t++) {
                const uint64_t ah = sdesc(tb + (uint32_t)t * 16384u);
                const uint64_t al = sdesc(tb + 49152u + (uint32_t)t * 16384u);
                const uint32_t dt = tmem + (uint32_t)t * 128u;
#pragma unroll
                for (int s = 0; s < 4; s++) mma_bf16_ss(dt, ah + 2 * s, bl + 2 * s, IDESC128_, 1u);
#pragma unroll
                for (int s = 0; s < 4; s++) mma_bf16_ss(dt, al + 2 * s, bh + 2 * s, IDESC128_, 1u);
            }
            TCGEN05_COMMIT(mbM[cur]);
            if (kt + 2 < KT_) {
                MBARRIER_WAIT_PARITY(mbM[cur], mph[cur]); mph[cur] ^= 1;
                load(cur, kt + 2);
            }
        }
        MBARRIER_WAIT_PARITY(mbM[0], mph[0]);
        MBARRIER_WAIT_PARITY(mbM[1], mph[1]);
    }
    __syncthreads();
    TCGEN05_FENCE_AFTER();

    const int tile = wid >> 2, sub = wid & 3;
    const int oc = tile * 128 + sub * 32 + lid;
    const float bv = bias[oc];
    float* op = out + ((size_t)b * OC_ + oc) * P_ + p0;
#pragma unroll
    for (int j = 0; j < 4; j++) {
        uint32_t r[32];
        TCGEN05_LD_X32(r, tmem + tile * 128 + j * 32);
        TCGEN05_WAIT_LD();
#pragma unroll
        for (int c = 0; c < 32; c += 4) {
            float4 v;
            v.x = __uint_as_float(r[c + 0]) + bv;
            v.y = __uint_as_float(r[c + 1]) + bv;
            v.z = __uint_as_float(r[c + 2]) + bv;
            v.w = __uint_as_float(r[c + 3]) + bv;
            *(float4*)(op + j * 32 + c) = v;
        }
    }
    TCGEN05_FENCE_BEFORE();
    __syncthreads();
    if (tid == 0) {
        MBAR_INVAL(mbH[0]); MBAR_INVAL(mbH[1]);
        MBAR_INVAL(mbLo[0]); MBAR_INVAL(mbLo[1]);
        MBAR_INVAL(mbM[0]); MBAR_INVAL(mbM[1]);
    }
    if (wid == 0) { TCGEN05_RELINQ(); TCGEN05_DEALLOC(tmem, 256); }
#endif
}

// ---------------- launch ----------------
extern "C" void kernel_launch(void* const* d_in, const int* in_sizes, int n_in,
                              void* d_out, int out_size) {
    const float* x    = (const float*)d_in[0];
    const float* ow   = (const float*)d_in[1];
    const float* ob   = (const float*)d_in[2];
    const float* wgt  = (const float*)d_in[3];
    const float* bias = (const float*)d_in[4];
    float* out = (float*)d_out;

    cudaFuncSetAttribute(k_gemm_tc,    cudaFuncAttributeMaxDynamicSharedMemorySize, 197632);
    cudaFuncSetAttribute(k_offconv_tc, cudaFuncAttributeMaxDynamicSharedMemorySize, OFF_SMEM);

    k_zero_border<<<dim3(260, B_), 64>>>();
    k_transpose<<<dim3(64, 2, B_), 256>>>(x);
    k_split<<<2592, 256>>>(wgt, ow);
    k_offconv_tc<<<dim3(32, B_), 256, OFF_SMEM>>>(ob);
    k_im2col_tc<<<dim3(P_ / 128, KT_, B_), 256>>>();
    k_gemm_tc<<<dim3(P_ / 128, B_), 256, 197632>>>(bias, out);
}